// round 1
// baseline (speedup 1.0000x reference)
#include <cuda_runtime.h>
#include <cuda_bf16.h>
#include <math.h>

#define BATCH 4
#define SEQ   512
#define DM    1024
#define NH    16
#define NL    8
#define VOCAB 32000
#define HDIM  64
#define DFF   4096
#define MROWS (BATCH*SEQ)   // 2048

// ---------------- scratch (static device globals; no allocation) ----------------
__device__ float g_x [MROWS*DM];
__device__ float g_t0[MROWS*DM];
__device__ float g_t1[MROWS*DM];
__device__ float g_t2[MROWS*DM];
__device__ float g_t3[MROWS*DM];
__device__ float g_f1[MROWS*DFF];

// ---------------- embedding + positional (pe indexed by BATCH, per reference) ----
__global__ void embed_kernel(const int* __restrict__ tokens,
                             const float* __restrict__ emb,
                             const float* __restrict__ pe,
                             float* __restrict__ x)
{
    int idx = blockIdx.x * blockDim.x + threadIdx.x;
    if (idx >= MROWS * DM) return;
    int d  = idx % DM;
    int nt = idx / DM;          // n*SEQ + t
    int n  = nt / SEQ;
    int tok = tokens[nt];
    x[idx] = emb[(size_t)tok * DM + d] + pe[(size_t)n * DM + d];
}

// ---------------- SGEMM: C(MxN) = A(MxK) @ B(KxN) + bias, optional ReLU ---------
// 128x128 block tile, BK=8, 256 threads, 8x8 per thread (two 4x4 quadrants).
#define BM 128
#define BN 128
#define BK 8
#define ASTR 132   // padded stride for As to kill store bank conflicts

template<bool RELU>
__global__ void __launch_bounds__(256)
sgemm_bias(const float* __restrict__ A, const float* __restrict__ B,
           const float* __restrict__ bias, float* __restrict__ C,
           int M, int Nn, int K)
{
    __shared__ float As[BK * ASTR];
    __shared__ float Bs[BK * BN];

    int tid = threadIdx.x;
    const float* Ab = A + (size_t)blockIdx.x * BM * K;
    const float* Bb = B + (size_t)blockIdx.y * BN;
    float*       Cb = C + (size_t)blockIdx.x * BM * Nn + (size_t)blockIdx.y * BN;

    int arow = tid >> 1;           // 0..127
    int acol = (tid & 1) * 4;      // 0 or 4
    int brow = tid >> 5;           // 0..7
    int bcol = (tid & 31) * 4;     // 0..124

    int tx = tid & 15;             // 0..15
    int ty = tid >> 4;             // 0..15

    float acc[8][8];
#pragma unroll
    for (int i = 0; i < 8; i++)
#pragma unroll
        for (int j = 0; j < 8; j++) acc[i][j] = 0.f;

    for (int k0 = 0; k0 < K; k0 += BK) {
        float4 a4 = *(const float4*)(Ab + (size_t)arow * K + k0 + acol);
        As[(acol + 0) * ASTR + arow] = a4.x;
        As[(acol + 1) * ASTR + arow] = a4.y;
        As[(acol + 2) * ASTR + arow] = a4.z;
        As[(acol + 3) * ASTR + arow] = a4.w;
        float4 b4 = *(const float4*)(Bb + (size_t)(k0 + brow) * Nn + bcol);
        *(float4*)(Bs + brow * BN + bcol) = b4;
        __syncthreads();

#pragma unroll
        for (int k = 0; k < BK; k++) {
            float4 a0 = *(const float4*)(As + k * ASTR + ty * 4);
            float4 a1 = *(const float4*)(As + k * ASTR + 64 + ty * 4);
            float4 b0 = *(const float4*)(Bs + k * BN + tx * 4);
            float4 b1 = *(const float4*)(Bs + k * BN + 64 + tx * 4);
            float ar[8] = {a0.x, a0.y, a0.z, a0.w, a1.x, a1.y, a1.z, a1.w};
            float br[8] = {b0.x, b0.y, b0.z, b0.w, b1.x, b1.y, b1.z, b1.w};
#pragma unroll
            for (int i = 0; i < 8; i++)
#pragma unroll
                for (int j = 0; j < 8; j++)
                    acc[i][j] += ar[i] * br[j];
        }
        __syncthreads();
    }

    // epilogue
#pragma unroll
    for (int ih = 0; ih < 2; ih++) {
#pragma unroll
        for (int ii = 0; ii < 4; ii++) {
            int row = ih * 64 + ty * 4 + ii;
#pragma unroll
            for (int jh = 0; jh < 2; jh++) {
                int col = jh * 64 + tx * 4;
                const float* bp = bias + (size_t)blockIdx.y * BN + col;
                float4 r;
                r.x = acc[ih * 4 + ii][jh * 4 + 0] + bp[0];
                r.y = acc[ih * 4 + ii][jh * 4 + 1] + bp[1];
                r.z = acc[ih * 4 + ii][jh * 4 + 2] + bp[2];
                r.w = acc[ih * 4 + ii][jh * 4 + 3] + bp[3];
                if (RELU) {
                    r.x = fmaxf(r.x, 0.f); r.y = fmaxf(r.y, 0.f);
                    r.z = fmaxf(r.z, 0.f); r.w = fmaxf(r.w, 0.f);
                }
                *(float4*)(Cb + (size_t)row * Nn + col) = r;
            }
        }
    }
}

// ---------------- causal attention (flash-style, fp32) --------------------------
// grid: (SEQ/128, NH, BATCH), 128 threads. Each thread owns one query row.
// smem: qs[128][65] | ks[64][65] | vs[64][65] | scs[128][65]
#define ATTN_SMEM ((128*65 + 64*65 + 64*65 + 128*65) * 4)

__global__ void __launch_bounds__(128)
attn_kernel(const float* __restrict__ q, const float* __restrict__ k,
            const float* __restrict__ v, float* __restrict__ o)
{
    extern __shared__ float sm[];
    float* qs  = sm;                  // 128*65
    float* ks  = qs + 128 * 65;       // 64*65
    float* vs  = ks + 64 * 65;        // 64*65
    float* scs = vs + 64 * 65;        // 128*65

    int n  = blockIdx.z;
    int h  = blockIdx.y;
    int qt = blockIdx.x;
    int tid = threadIdx.x;
    int r = qt * 128 + tid;           // global query row (< SEQ)

    // load q tile (128 rows x 64 cols), coalesced
    for (int i = tid; i < 128 * 16; i += 128) {
        int row = i >> 4, c4 = (i & 15) * 4;
        float4 t = *(const float4*)(q + ((size_t)(n * SEQ + qt * 128 + row)) * DM + h * HDIM + c4);
        qs[row * 65 + c4 + 0] = t.x; qs[row * 65 + c4 + 1] = t.y;
        qs[row * 65 + c4 + 2] = t.z; qs[row * 65 + c4 + 3] = t.w;
    }
    __syncthreads();

    float qreg[64];
#pragma unroll
    for (int d = 0; d < 64; d++) qreg[d] = qs[tid * 65 + d] * 0.125f;  // 1/sqrt(64)

    float m = -1e30f, l = 0.f;
    float acc[64];
#pragma unroll
    for (int d = 0; d < 64; d++) acc[d] = 0.f;

    int smax = qt * 128 + 127;
    for (int s0 = 0; s0 <= smax; s0 += 64) {
        // load K,V tiles (64 x 64)
        for (int i = tid; i < 64 * 16; i += 128) {
            int row = i >> 4, c4 = (i & 15) * 4;
            size_t base = ((size_t)(n * SEQ + s0 + row)) * DM + h * HDIM + c4;
            float4 kk = *(const float4*)(k + base);
            ks[row * 65 + c4 + 0] = kk.x; ks[row * 65 + c4 + 1] = kk.y;
            ks[row * 65 + c4 + 2] = kk.z; ks[row * 65 + c4 + 3] = kk.w;
            float4 vv = *(const float4*)(v + base);
            vs[row * 65 + c4 + 0] = vv.x; vs[row * 65 + c4 + 1] = vv.y;
            vs[row * 65 + c4 + 2] = vv.z; vs[row * 65 + c4 + 3] = vv.w;
        }
        __syncthreads();

        // scores for this tile (per-thread private row of scs)
        float tmax = -1e30f;
        for (int s = 0; s < 64; s++) {
            float sc;
            if (s0 + s > r) {
                sc = -1e30f;
            } else {
                sc = 0.f;
#pragma unroll
                for (int d = 0; d < 64; d++) sc += qreg[d] * ks[s * 65 + d];
            }
            scs[tid * 65 + s] = sc;
            tmax = fmaxf(tmax, sc);
        }

        float nm = fmaxf(m, tmax);
        float cf = __expf(m - nm);
        l *= cf;
#pragma unroll
        for (int d = 0; d < 64; d++) acc[d] *= cf;

        for (int s = 0; s < 64; s++) {
            float p = __expf(scs[tid * 65 + s] - nm);
            l += p;
#pragma unroll
            for (int d = 0; d < 64; d++) acc[d] += p * vs[s * 65 + d];
        }
        m = nm;
        __syncthreads();
    }

    float inv = 1.f / l;
    float* op = o + ((size_t)(n * SEQ + r)) * DM + h * HDIM;
#pragma unroll
    for (int d0 = 0; d0 < 64; d0 += 4) {
        float4 t;
        t.x = acc[d0 + 0] * inv; t.y = acc[d0 + 1] * inv;
        t.z = acc[d0 + 2] * inv; t.w = acc[d0 + 3] * inv;
        *(float4*)(op + d0) = t;
    }
}

// ---------------- residual + LayerNorm: x += LN(o)*g + b ------------------------
__global__ void __launch_bounds__(256)
ln_residual(float* __restrict__ x, const float* __restrict__ o,
            const float* __restrict__ g, const float* __restrict__ b)
{
    __shared__ float red[256];
    __shared__ float s_mean, s_rstd;
    int row = blockIdx.x;
    int tid = threadIdx.x;
    const float* orow = o + (size_t)row * DM;
    float*       xrow = x + (size_t)row * DM;

    float s = 0.f;
    for (int d = tid; d < DM; d += 256) s += orow[d];
    red[tid] = s; __syncthreads();
    for (int off = 128; off > 0; off >>= 1) {
        if (tid < off) red[tid] += red[tid + off];
        __syncthreads();
    }
    if (tid == 0) s_mean = red[0] * (1.f / DM);
    __syncthreads();
    float mean = s_mean;

    float vv = 0.f;
    for (int d = tid; d < DM; d += 256) { float t = orow[d] - mean; vv += t * t; }
    red[tid] = vv; __syncthreads();
    for (int off = 128; off > 0; off >>= 1) {
        if (tid < off) red[tid] += red[tid + off];
        __syncthreads();
    }
    if (tid == 0) s_rstd = rsqrtf(red[0] * (1.f / DM) + 1e-5f);
    __syncthreads();
    float rstd = s_rstd;

    for (int d = tid; d < DM; d += 256)
        xrow[d] += (orow[d] - mean) * rstd * g[d] + b[d];
}

// ---------------- launch --------------------------------------------------------
extern "C" void kernel_launch(void* const* d_in, const int* in_sizes, int n_in,
                              void* d_out, int out_size)
{
    const int*   tokens = (const int*)  d_in[0];
    const float* emb    = (const float*)d_in[1];
    const float* pe     = (const float*)d_in[2];
    const float* Wq     = (const float*)d_in[3];
    const float* bq     = (const float*)d_in[4];
    const float* Wk     = (const float*)d_in[5];
    const float* bk     = (const float*)d_in[6];
    const float* Wv     = (const float*)d_in[7];
    const float* bv     = (const float*)d_in[8];
    const float* Wo     = (const float*)d_in[9];
    const float* bo     = (const float*)d_in[10];
    const float* g1     = (const float*)d_in[11];
    const float* be1    = (const float*)d_in[12];
    const float* W1     = (const float*)d_in[13];
    const float* b1     = (const float*)d_in[14];
    const float* W2     = (const float*)d_in[15];
    const float* b2     = (const float*)d_in[16];
    const float* g2     = (const float*)d_in[17];
    const float* be2    = (const float*)d_in[18];
    const float* Wfc    = (const float*)d_in[19];
    const float* bfc    = (const float*)d_in[20];
    float* out = (float*)d_out;

    float *x, *t0, *t1, *t2, *t3, *f1;
    cudaGetSymbolAddress((void**)&x,  g_x);
    cudaGetSymbolAddress((void**)&t0, g_t0);
    cudaGetSymbolAddress((void**)&t1, g_t1);
    cudaGetSymbolAddress((void**)&t2, g_t2);
    cudaGetSymbolAddress((void**)&t3, g_t3);
    cudaGetSymbolAddress((void**)&f1, g_f1);

    cudaFuncSetAttribute(attn_kernel,
                         cudaFuncAttributeMaxDynamicSharedMemorySize, ATTN_SMEM);

    embed_kernel<<<(MROWS * DM + 255) / 256, 256>>>(tokens, emb, pe, x);

    dim3 gDD(MROWS / BM, DM / BN);     // (16, 8)
    dim3 gDF(MROWS / BM, DFF / BN);    // (16, 32)
    dim3 gAttn(SEQ / 128, NH, BATCH);  // (4, 16, 4)

    for (int l = 0; l < NL; l++) {
        const float* wq = Wq + (size_t)l * DM * DM;
        const float* wk = Wk + (size_t)l * DM * DM;
        const float* wv = Wv + (size_t)l * DM * DM;
        const float* wo = Wo + (size_t)l * DM * DM;
        const float* w1 = W1 + (size_t)l * DM * DFF;
        const float* w2 = W2 + (size_t)l * DFF * DM;

        sgemm_bias<false><<<gDD, 256>>>(x, wq, bq + l * DM, t0, MROWS, DM, DM);
        sgemm_bias<false><<<gDD, 256>>>(x, wk, bk + l * DM, t1, MROWS, DM, DM);
        sgemm_bias<false><<<gDD, 256>>>(x, wv, bv + l * DM, t2, MROWS, DM, DM);

        attn_kernel<<<gAttn, 128, ATTN_SMEM>>>(t0, t1, t2, t3);

        sgemm_bias<false><<<gDD, 256>>>(t3, wo, bo + l * DM, t0, MROWS, DM, DM);
        ln_residual<<<MROWS, 256>>>(x, t0, g1 + l * DM, be1 + l * DM);

        sgemm_bias<true ><<<gDF, 256>>>(x,  w1, b1 + l * DFF, f1, MROWS, DFF, DM);
        sgemm_bias<false><<<gDD, 256>>>(f1, w2, b2 + l * DM,  t0, MROWS, DM, DFF);
        ln_residual<<<MROWS, 256>>>(x, t0, g2 + l * DM, be2 + l * DM);
    }

    dim3 gV(MROWS / BM, VOCAB / BN);   // (16, 250)
    sgemm_bias<false><<<gV, 256>>>(x, Wfc, bfc, out, MROWS, VOCAB, DM);
}